// round 5
// baseline (speedup 1.0000x reference)
#include <cuda_runtime.h>
#include <cstdint>

// ---------------------------------------------------------------------------
// SCAConv decomposition (same math as R2/R3):
// out[b,o,l] = bias[o] + sum_i xu*kernel[o,i] + sum_i xu*b2[(l&31)*144+i]
//            + sum_j H[o*128+(l>>5), j] * G[b,l,j]
// G[b,l,j] = sum_i xu[b,i,l] * W2[((l&31)*144+i)*32 + j]
//
// R4: occupancy fix. Block = (lh, batch-half of 4), grid 256, 512 threads,
// thread tile 4 batches x 4 cols with fma.rn.f32x2 over the batch pairs.
// smem 65.9KB + launch_bounds(512,2) -> 2 CTAs/SM (32 warps, occ 50%).
// ---------------------------------------------------------------------------

#define XS_OFF   0
#define XS_RSTR  35
#define XS_SIZE  (48*XS_RSTR*4)        // 6720 floats, 4 batches innermost
#define HS_OFF   (XS_OFF + XS_SIZE)
#define HS_SIZE  (32*32)
#define BIAS_OFF (HS_OFF + HS_SIZE)
#define BIAS_SIZE 32
#define CS_OFF   (BIAS_OFF + BIAS_SIZE)
#define CS_LSTR  68                    // per-lm: 32 G + 32 conv + 1 t + 3 pad
#define CS_BSTR  (32*CS_LSTR)
#define CS_SIZE  (4*CS_BSTR)           // 8704
#define SMEM_FLOATS (CS_OFF + CS_SIZE) // 16480 floats = 65.9 KB

__device__ float g_kT[144*32];         // kernel transposed: kT[i][o]

__global__ void prep_kernel(const float* __restrict__ kern) {
    int idx = blockIdx.x * 256 + threadIdx.x;
    if (idx < 4608) {
        int i = idx >> 5, o = idx & 31;
        g_kT[idx] = kern[o*144 + i];
    }
}

typedef unsigned long long ull;

#define PACK2(d, s)   asm("mov.b64 %0, {%1, %1};" : "=l"(d) : "f"(s))
#define UNPACK2(lo, hi, v) asm("mov.b64 {%0, %1}, %2;" : "=f"(lo), "=f"(hi) : "l"(v))
#define FMA2(acc, a, b) asm("fma.rn.f32x2 %0, %1, %2, %0;" : "+l"(acc) : "l"(a), "l"(b))

__global__ __launch_bounds__(512, 2)
void sca_kernel(const float* __restrict__ x, const float* __restrict__ bias,
                const float* __restrict__ cpar,
                const float* __restrict__ W1, const float* __restrict__ b1,
                const float* __restrict__ W2, const float* __restrict__ b2,
                float* __restrict__ out)
{
    extern __shared__ float sm[];
    float* xs = sm + XS_OFF;
    float* Hs = sm + HS_OFF;
    float* bs = sm + BIAS_OFF;
    float* Cs = sm + CS_OFF;

    const int tid = threadIdx.x;
    const int lh  = blockIdx.x >> 1;   // 0..127 (pairs of blocks share lh -> L2 dedup)
    const int bh  = blockIdx.x & 1;    // batch half: batches bh*4 .. bh*4+3
    const int R   = lh >> 1;
    const int C0  = (lh & 1) * 32;

    // ---------- setup: x patch for 4 batches, batch-innermost ----------
    for (int idx = tid; idx < 4*16*3*34; idx += 512) {
        int cc = idx % 34;
        int t2 = idx / 34;
        int kr = t2 % 3;  t2 /= 3;
        int c  = t2 % 16;
        int b  = t2 / 16;              // 0..3
        int r   = R - 1 + kr;
        int col = C0 - 1 + cc;
        float v = 0.f;
        if (r >= 0 && r < 64 && col >= 0 && col < 64)
            v = x[(((bh*4 + b)*16 + c)*64 + r)*64 + col];
        xs[((c*3 + kr)*XS_RSTR + cc)*4 + b] = v;
    }

    // ---------- H rows: H[o*128+lh][j] ----------
    {
        int o  = tid >> 4;
        int jh = tid & 15;
        int p  = o*128 + lh;
        float inp[12];
        inp[0] = (float)(p >> 6) * (1.f/64.f);
        inp[1] = 1.f - inp[0];
        inp[2] = (float)(p & 63) * (1.f/64.f);
        inp[3] = 1.f - inp[2];
        #pragma unroll
        for (int k = 0; k < 8; k++) inp[4+k] = cpar[k];
        #pragma unroll
        for (int jj = 0; jj < 2; jj++) {
            int j = jh*2 + jj;
            float s = b1[j];
            #pragma unroll
            for (int k = 0; k < 12; k++) s += W1[j*12 + k] * inp[k];
            Hs[o*32 + j] = fmaxf(s, 0.f);
        }
    }
    if (tid < 32) bs[tid] = bias[tid];
    __syncthreads();

    // ---------- main loop: 4 batches x 4 cols per thread, f32x2 packed ----------
    // tid = part*256 + lm*8 + cg ; part 0: G cols j = cg*4..+3 (W2, L2-hot)
    //                              part 1: conv cols o = cg*4..+3 (g_kT, L1-hot)
    {
        const int part = tid >> 8;
        const int t    = tid & 255;
        const int lm   = t >> 3;
        const int cg   = t & 7;

        const float* wp = part ? (g_kT + cg*4) : (W2 + lm*4608 + cg*4);
        const float* xp = xs + lm*4;

        ull acc[4][2];   // [col n][batch pair bp]
        #pragma unroll
        for (int n = 0; n < 4; n++) { acc[n][0] = 0ull; acc[n][1] = 0ull; }

        for (int c = 0; c < 16; ++c) {
            const float* xc = xp + c*(3*XS_RSTR*4);
            const float* wc = wp + c*(9*32);
            #pragma unroll
            for (int kr = 0; kr < 3; ++kr) {
                #pragma unroll
                for (int kc = 0; kc < 3; ++kc) {
                    ulonglong2 xa = *(const ulonglong2*)(xc + (kr*XS_RSTR + kc)*4);
                    float4 w = *(const float4*)(wc + (kr*3 + kc)*32);
                    ull wpk[4];
                    PACK2(wpk[0], w.x); PACK2(wpk[1], w.y);
                    PACK2(wpk[2], w.z); PACK2(wpk[3], w.w);
                    #pragma unroll
                    for (int n = 0; n < 4; n++) {
                        FMA2(acc[n][0], xa.x, wpk[n]);
                        FMA2(acc[n][1], xa.y, wpk[n]);
                    }
                }
            }
        }

        float f[4][4];   // [batch][col]
        #pragma unroll
        for (int n = 0; n < 4; n++) {
            UNPACK2(f[0][n], f[1][n], acc[n][0]);
            UNPACK2(f[2][n], f[3][n], acc[n][1]);
        }
        float* cb = Cs + lm*CS_LSTR + part*32 + cg*4;
        #pragma unroll
        for (int b = 0; b < 4; b++)
            *(float4*)(cb + b*CS_BSTR) = make_float4(f[b][0], f[b][1], f[b][2], f[b][3]);
    }

    // ---------- t-term tail: t[b][lm] = sum_i xu * b2[lm*144+i] ----------
    if (tid < 32) {
        int lm2 = tid;
        const float* xp2 = xs + lm2*4;
        const float* bp2 = b2 + lm2*144;
        ull ta[2] = {0ull, 0ull};
        for (int c = 0; c < 16; ++c) {
            #pragma unroll
            for (int kr = 0; kr < 3; ++kr) {
                #pragma unroll
                for (int kc = 0; kc < 3; ++kc) {
                    ulonglong2 xa = *(const ulonglong2*)(xp2 + (c*3*XS_RSTR + kr*XS_RSTR + kc)*4);
                    ull bv; PACK2(bv, bp2[c*9 + kr*3 + kc]);
                    FMA2(ta[0], xa.x, bv); FMA2(ta[1], xa.y, bv);
                }
            }
        }
        float t0, t1, t2, t3;
        UNPACK2(t0, t1, ta[0]); UNPACK2(t2, t3, ta[1]);
        Cs[0*CS_BSTR + lm2*CS_LSTR + 64] = t0;
        Cs[1*CS_BSTR + lm2*CS_LSTR + 64] = t1;
        Cs[2*CS_BSTR + lm2*CS_LSTR + 64] = t2;
        Cs[3*CS_BSTR + lm2*CS_LSTR + 64] = t3;
    }
    __syncthreads();

    // ---------- epilogue: out = bias + t + conv + H·G ----------
    {
        int b   = tid >> 7;            // 0..3 (local batch)
        int oq  = (tid >> 5) & 3;      // o-octet: o = oq*8 .. +7
        int lm3 = tid & 31;            // lanes = consecutive lm -> coalesced
        const float* cb = Cs + b*CS_BSTR + lm3*CS_LSTR;

        float g[32];
        #pragma unroll
        for (int q = 0; q < 8; q++) {
            float4 v = *(const float4*)(cb + q*4);
            g[q*4+0] = v.x; g[q*4+1] = v.y; g[q*4+2] = v.z; g[q*4+3] = v.w;
        }
        float cw[8];
        #pragma unroll
        for (int q = 0; q < 2; q++) {
            float4 v = *(const float4*)(cb + 32 + oq*8 + q*4);
            cw[q*4+0] = v.x; cw[q*4+1] = v.y; cw[q*4+2] = v.z; cw[q*4+3] = v.w;
        }
        float tv = cb[64];

        float* ob = out + (bh*4 + b)*(32*4096) + (oq*8)*4096 + lh*32 + lm3;
        #pragma unroll
        for (int oo = 0; oo < 8; oo++) {
            int o = oq*8 + oo;
            float s = bs[o] + tv + cw[oo];
            const float4* h4 = (const float4*)(Hs + o*32);
            #pragma unroll
            for (int q = 0; q < 8; q++) {
                float4 h = h4[q];
                s += h.x*g[q*4] + h.y*g[q*4+1] + h.z*g[q*4+2] + h.w*g[q*4+3];
            }
            ob[oo*4096] = s;
        }
    }
}

extern "C" void kernel_launch(void* const* d_in, const int* in_sizes, int n_in,
                              void* d_out, int out_size)
{
    const float* x    = (const float*)d_in[0];   // (8,16,64,64)
    const float* kern = (const float*)d_in[1];   // (32,144)
    const float* bias = (const float*)d_in[2];   // (32,)
    const float* cpar = (const float*)d_in[3];   // (1,8)
    const float* W1   = (const float*)d_in[4];   // (32,12)
    const float* b1   = (const float*)d_in[5];   // (32,)
    const float* W2   = (const float*)d_in[6];   // (4608,32)
    const float* b2   = (const float*)d_in[7];   // (4608,)
    float* out = (float*)d_out;                  // (8,32,64,64)

    prep_kernel<<<18, 256>>>(kern);
    cudaFuncSetAttribute(sca_kernel, cudaFuncAttributeMaxDynamicSharedMemorySize,
                         SMEM_FLOATS * 4);
    sca_kernel<<<256, 512, SMEM_FLOATS * 4>>>(x, bias, cpar, W1, b1, W2, b2, out);
}